// round 17
// baseline (speedup 1.0000x reference)
#include <cuda_runtime.h>
#include <cuda_fp16.h>
#include <cstdint>
#include <math.h>

// Problem constants
#define Bb 8
#define Cc 1152
#define Hh 32
#define Ww 32
#define Nn 1024   // H*W
#define IBLK 64   // row-blocks per batch in k_row2 (Nn / ROWS_PER_BLK)

// ---------------- scratch (static device globals: allowed) ----------------
__device__ __align__(16) float g_alpha[Bb * Nn];
__device__ __align__(16) float g_beta [Bb * Nn];
__device__ __align__(16) float g_gamma[Bb * Nn];
__device__ __align__(16) float g_part [(size_t)IBLK * Bb * Nn]; // partial column sums
__device__ __align__(16) float g_cinv [Bb * Nn];                // 1 / csum
__device__ __align__(16) float g_colsum[Bb * Cc];               // colsum_c = sum_j F[c,j]
__device__ __align__(16) __half g_U[(size_t)Bb * Nn * Nn];      // u = 1 - exp(-s), fp16
__device__ __align__(16) __half g_F[(size_t)Bb * Cc * Nn];      // F = f_src / csum, fp16

// ======================= generic-PTX helpers ===============================
__device__ __forceinline__ uint32_t smem_to_u32(const void* p) {
    uint32_t a;
    asm("{ .reg .u64 t; cvta.to.shared.u64 t, %1; cvt.u32.u64 %0, t; }" : "=r"(a) : "l"(p));
    return a;
}
__device__ __forceinline__ void cp16(uint32_t s, const void* g) {
    asm volatile("cp.async.cg.shared.global [%0], [%1], 16;" :: "r"(s), "l"(g));
}
#define CP_COMMIT() asm volatile("cp.async.commit_group;" ::: "memory")
#define CP_WAIT(n)  asm volatile("cp.async.wait_group %0;" :: "n"(n) : "memory")

__device__ __forceinline__ void ldsm_x4(uint32_t* r, uint32_t addr) {
    asm volatile("ldmatrix.sync.aligned.m8n8.x4.shared.b16 {%0,%1,%2,%3}, [%4];"
                 : "=r"(r[0]), "=r"(r[1]), "=r"(r[2]), "=r"(r[3]) : "r"(addr));
}
__device__ __forceinline__ void mma16816h(float* c, const uint32_t* a, const uint32_t* b) {
    asm volatile(
        "mma.sync.aligned.m16n8k16.row.col.f32.f16.f16.f32 "
        "{%0,%1,%2,%3}, {%4,%5,%6,%7}, {%8,%9}, {%0,%1,%2,%3};"
        : "+f"(c[0]), "+f"(c[1]), "+f"(c[2]), "+f"(c[3])
        : "r"(a[0]), "r"(a[1]), "r"(a[2]), "r"(a[3]), "r"(b[0]), "r"(b[1]));
}

// ---------------- kernel 1: fundamental matrix + per-line coefficients ----
__global__ void k_coef(const float* __restrict__ K1, const float* __restrict__ K2,
                       const float* __restrict__ R,  const float* __restrict__ T)
{
    int b = blockIdx.x;
    __shared__ float F[9];
    if (threadIdx.x == 0) {
        const float* k1 = K1 + b * 9;
        const float* k2 = K2 + b * 9;
        const float* r  = R  + b * 9;
        const float* tv = T  + b * 3;
        float t0 = tv[0], t1 = tv[1], t2 = tv[2];
        float E[9];
        #pragma unroll
        for (int c = 0; c < 3; c++) {
            float r0 = r[0 * 3 + c], r1 = r[1 * 3 + c], r2 = r[2 * 3 + c];
            E[0 * 3 + c] = -t2 * r1 + t1 * r2;
            E[1 * 3 + c] =  t2 * r0 - t0 * r2;
            E[2 * 3 + c] = -t1 * r0 + t0 * r1;
        }
        float fx2 = k2[0], fy2 = k2[4], cx2 = k2[2], cy2 = k2[5];
        float M[9];
        #pragma unroll
        for (int c = 0; c < 3; c++) {
            M[0 * 3 + c] = E[0 * 3 + c] / fx2;
            M[1 * 3 + c] = E[1 * 3 + c] / fy2;
            M[2 * 3 + c] = -cx2 / fx2 * E[0 * 3 + c] - cy2 / fy2 * E[1 * 3 + c] + E[2 * 3 + c];
        }
        float fx1 = k1[0], fy1 = k1[4], cx1 = k1[2], cy1 = k1[5];
        #pragma unroll
        for (int rr = 0; rr < 3; rr++) {
            float m0 = M[rr * 3 + 0], m1 = M[rr * 3 + 1], m2 = M[rr * 3 + 2];
            F[rr * 3 + 0] = m0 / fx1;
            F[rr * 3 + 1] = m1 / fy1;
            F[rr * 3 + 2] = -cx1 / fx1 * m0 - cy1 / fy1 * m1 + m2;
        }
    }
    __syncthreads();
    for (int j = threadIdx.x; j < Nn; j += blockDim.x) {
        float x = (float)(j / Ww);
        float y = (float)(j % Ww);
        float l0 = F[0] * x + F[1] * y + F[2];
        float l1 = F[3] * x + F[4] * y + F[5];
        float l2 = F[6] * x + F[7] * y + F[8];
        float ap = l0 / l2;
        float bp = l1 / l2;
        float rn = rsqrtf(ap * ap + bp * bp);
        g_alpha[b * Nn + j] = ap * rn;
        g_beta [b * Nn + j] = bp * rn;
        g_gamma[b * Nn + j] = rn;
    }
}

// ---------------- kernel 2: fused row-softmax -> u = 1-exp(-s) fp16 ------
// (R11-proven block version)
#define ROWS_PER_BLK 16
__global__ void __launch_bounds__(256) k_row2()
{
    int b  = blockIdx.y;
    int ib = blockIdx.x;
    int i0 = ib * ROWS_PER_BLK;
    const float* al = g_alpha + b * Nn;
    const float* be = g_beta  + b * Nn;
    const float* ga = g_gamma + b * Nn;
    __half* Up = g_U + (size_t)b * Nn * Nn;

    __shared__ float redm[8];
    __shared__ float redz[8];

    float A4[4], B4[4], G4[4];
    float cacc[4];
    #pragma unroll
    for (int k = 0; k < 4; k++) {
        int j = threadIdx.x + k * 256;
        A4[k] = al[j]; B4[k] = be[j]; G4[k] = ga[j];
        cacc[k] = 0.0f;
    }

    for (int r = 0; r < ROWS_PER_BLK; r++) {
        int i = i0 + r;
        float x = (float)(i / Ww);
        float y = (float)(i % Ww);
        float v[4];
        float m = -1e30f;
        #pragma unroll
        for (int k = 0; k < 4; k++) {
            v[k] = 5.0f * fabsf(fmaf(A4[k], x, fmaf(B4[k], y, G4[k])));
            m = fmaxf(m, v[k]);
        }
        #pragma unroll
        for (int o = 16; o; o >>= 1) m = fmaxf(m, __shfl_xor_sync(0xffffffffu, m, o));
        if ((threadIdx.x & 31) == 0) redm[threadIdx.x >> 5] = m;
        __syncthreads();
        float bm = redm[0];
        #pragma unroll
        for (int w = 1; w < 8; w++) bm = fmaxf(bm, redm[w]);

        float e1[4];
        float z = 0.0f;
        #pragma unroll
        for (int k = 0; k < 4; k++) { e1[k] = __expf(v[k] - bm); z += e1[k]; }
        #pragma unroll
        for (int o = 16; o; o >>= 1) z += __shfl_xor_sync(0xffffffffu, z, o);
        if ((threadIdx.x & 31) == 0) redz[threadIdx.x >> 5] = z;
        __syncthreads();
        float bz = 0.0f;
        #pragma unroll
        for (int w = 0; w < 8; w++) bz += redz[w];
        float inv = 1.0f / bz;

        size_t rowoff = (size_t)i * Nn;   // batch offset lives in Up pointer
        #pragma unroll
        for (int k = 0; k < 4; k++) {
            float s = e1[k] * inv;               // row-softmax value in (0,1]
            float e = __expf(-s);                // column-softmax numerator (shift 0)
            cacc[k] += e;
            float u = 1.0f - e;                  // GEMM operand: out = colsum - U@F^T
            int j = threadIdx.x + k * 256;
            Up[rowoff + j] = __float2half_rn(u);
        }
    }

    size_t poff = ((size_t)(b * IBLK + ib)) * Nn;
    #pragma unroll
    for (int k = 0; k < 4; k++)
        g_part[poff + threadIdx.x + k * 256] = cacc[k];
}

// ---------------- kernel 2b: cinv = 1 / sum_ib part ------------------------
__global__ void k_cinv()
{
    int i = blockIdx.x * blockDim.x + threadIdx.x;
    if (i >= Bb * Nn) return;
    int b = i / Nn, j = i % Nn;
    float s = 0.0f;
    #pragma unroll 8
    for (int ib = 0; ib < IBLK; ib++)
        s += g_part[((size_t)(b * IBLK + ib)) * Nn + j];
    g_cinv[i] = 1.0f / s;
}

// ---------------- kernel 3: F = f/csum -> fp16; colsum_c = sum_j F (fp32) --
// (R16-proven: packed f16x2 converts, deferred reduction, 2 barriers/block)
__global__ void __launch_bounds__(256) k_conv_f(const float* __restrict__ f)
{
    int b  = blockIdx.y;
    int c0 = blockIdx.x * 4;
    int tid = threadIdx.x;
    const float* ci = g_cinv + b * Nn + tid * 4;
    float cv0 = ci[0], cv1 = ci[1], cv2 = ci[2], cv3 = ci[3];
    __shared__ float red[4][8];

    #pragma unroll
    for (int r = 0; r < 4; r++) {
        int c = c0 + r;
        size_t rowbase = ((size_t)(b * Cc + c)) * Nn;
        float4 v = *(const float4*)(f + rowbase + tid * 4);
        v.x *= cv0; v.y *= cv1; v.z *= cv2; v.w *= cv3;

        __half2 h0 = __floats2half2_rn(v.x, v.y);
        __half2 h1 = __floats2half2_rn(v.z, v.w);
        uint2 pk;
        pk.x = *(const uint32_t*)&h0;
        pk.y = *(const uint32_t*)&h1;
        *(uint2*)(g_F + rowbase + tid * 4) = pk;

        float sm = (v.x + v.y) + (v.z + v.w);   // fp32 colsum contribution
        #pragma unroll
        for (int o = 16; o; o >>= 1) sm += __shfl_xor_sync(0xffffffffu, sm, o);
        if ((tid & 31) == 0) red[r][tid >> 5] = sm;
    }
    __syncthreads();
    if (tid < 4) {
        float t = 0.0f;
        #pragma unroll
        for (int w = 0; w < 8; w++) t += red[tid][w];
        g_colsum[b * Cc + c0 + tid] = t;
    }
}

// ---------------- kernel 4: fp16 mma GEMM, out = colsum - U @ F^T ---------
// NEW geometry: CTA tile M=256 (i) x N=128 (c), 512 threads = 16 warps in a
// 4x4 warp grid (warp tile 64x32 — per-warp inner code identical to the
// proven R11 kernel). Double-buffered cp.async; stage = U 256x64 (32KB) +
// F 128x64 (16KB) = 48KB, x2 = 96KB SMEM. Two barriers now amortize 2x the
// MACs, attacking the measured 23% non-overlap residual. 16 warps/SM kept.
#define U_TILE_B 32768          // 256x64 fp16 (swizzled, 128B rows)
#define F_TILE_B 16384          // 128x64 fp16
#define STAGE_B  (U_TILE_B + F_TILE_B)   // 49152
#define GEMM_SMEM (2 * STAGE_B)          // 98304
#define NSTAGE   (Nn / 64)      // 16

__global__ void __launch_bounds__(512, 1) k_gemm_mma(float* __restrict__ out)
{
    extern __shared__ char smem[];
    const uint32_t sb = smem_to_u32(smem);
    const int tid  = threadIdx.x;
    const int wid  = tid >> 5;          // 0..15
    const int lane = tid & 31;
    const int b    = blockIdx.z;
    const int n0   = blockIdx.x * 128;   // c tile
    const int m0   = blockIdx.y * 256;   // i tile

    const __half* Up = g_U + (size_t)b * Nn * Nn;
    const __half* Fp = g_F + (size_t)b * Cc * Nn;

    // MMA thread geometry: warp (warp_m, warp_n) owns 64x32 of the 256x128 tile
    const int warp_m = wid & 3;        // 0..3 -> 64-row band
    const int warp_n = wid >> 2;       // 0..3 -> 32-col band
    const int g  = lane >> 3;          // ldmatrix address group 0..3
    const int r  = lane & 7;
    uint32_t arow[4], brow[2];
    #pragma unroll
    for (int mt = 0; mt < 4; mt++)
        arow[mt] = (uint32_t)((warp_m * 64 + mt * 16 + (g & 1) * 8 + r) * 128);
    #pragma unroll
    for (int p = 0; p < 2; p++)
        brow[p] = (uint32_t)((warp_n * 32 + p * 16 + (g >> 1) * 8 + r) * 128);
    const uint32_t ka_half = (uint32_t)((g >> 1) << 4);
    const uint32_t kb_half = (uint32_t)((g & 1) << 4);
    const uint32_t rx = (uint32_t)(r << 4);

    float acc[4][4][4];
    #pragma unroll
    for (int mt = 0; mt < 4; mt++)
        #pragma unroll
        for (int nt = 0; nt < 4; nt++)
            #pragma unroll
            for (int q = 0; q < 4; q++) acc[mt][nt][q] = 0.0f;

    // producer: U = 2048 16B chunks (4/thread), F = 1024 chunks (2/thread)
    auto issue_load = [&](int buf, int s) {
        uint32_t base = sb + (uint32_t)buf * STAGE_B;
        int k0 = s * 64;
        #pragma unroll
        for (int q = 0; q < 4; q++) {
            int id  = tid + q * 512;
            int row = id >> 3;
            int c   = id & 7;
            uint32_t soff = (uint32_t)(row * 128 + ((16 * c) ^ ((row & 7) << 4)));
            cp16(base + soff, Up + (size_t)(m0 + row) * Nn + k0 + c * 8);
        }
        #pragma unroll
        for (int q = 0; q < 2; q++) {
            int id  = tid + q * 512;
            int row = id >> 3;
            int c   = id & 7;
            uint32_t soff = (uint32_t)(row * 128 + ((16 * c) ^ ((row & 7) << 4)));
            cp16(base + U_TILE_B + soff, Fp + (size_t)(n0 + row) * Nn + k0 + c * 8);
        }
    };

    issue_load(0, 0);
    CP_COMMIT();

    int buf = 0;
    for (int s = 0; s < NSTAGE; s++) {
        if (s + 1 < NSTAGE) {
            issue_load(buf ^ 1, s + 1);
            CP_COMMIT();
            CP_WAIT(1);
        } else {
            CP_WAIT(0);
        }
        __syncthreads();

        uint32_t bU = sb + (uint32_t)buf * STAGE_B;
        uint32_t bF = bU + U_TILE_B;

        #pragma unroll
        for (int kk = 0; kk < 4; kk++) {
            uint32_t ka = ((uint32_t)(kk * 32) + ka_half) ^ rx;
            uint32_t kb = ((uint32_t)(kk * 32) + kb_half) ^ rx;
            uint32_t ur[4][4];
            #pragma unroll
            for (int mt = 0; mt < 4; mt++)
                ldsm_x4(ur[mt], bU + arow[mt] + ka);
            uint32_t fr[2][4];
            #pragma unroll
            for (int p = 0; p < 2; p++)
                ldsm_x4(fr[p], bF + brow[p] + kb);
            #pragma unroll
            for (int mt = 0; mt < 4; mt++) {
                #pragma unroll
                for (int nt = 0; nt < 4; nt++) {
                    const uint32_t* fb = &fr[nt >> 1][(nt & 1) * 2];
                    mma16816h(acc[mt][nt], ur[mt], fb);
                }
            }
        }
        __syncthreads();
        buf ^= 1;
    }

    // ---- epilogue: out[i,c] = colsum[c] - acc ----
    float* Og = out + (size_t)b * Nn * Cc;
    const float* cs = g_colsum + b * Cc;
    const int rbase = m0 + warp_m * 64 + (lane >> 2);
    const int cbase = n0 + warp_n * 32 + (lane & 3) * 2;
    #pragma unroll
    for (int nt = 0; nt < 4; nt++) {
        int col = cbase + nt * 8;
        float cs0 = cs[col];
        float cs1 = cs[col + 1];
        #pragma unroll
        for (int mt = 0; mt < 4; mt++) {
            int row = rbase + mt * 16;
            float2 v0 = make_float2(cs0 - acc[mt][nt][0], cs1 - acc[mt][nt][1]);
            float2 v1 = make_float2(cs0 - acc[mt][nt][2], cs1 - acc[mt][nt][3]);
            *(float2*)(Og + (size_t)row * Cc + col)       = v0;
            *(float2*)(Og + (size_t)(row + 8) * Cc + col) = v1;
        }
    }
}

// ---------------- entry point ---------------------------------------------
extern "C" void kernel_launch(void* const* d_in, const int* in_sizes, int n_in,
                              void* d_out, int out_size)
{
    // metadata order: f_tar(0, unused), f_src(1), K1(2), K2(3), R(4), t(5)
    const float* f_src = (const float*)d_in[1];
    const float* K1    = (const float*)d_in[2];
    const float* K2    = (const float*)d_in[3];
    const float* R     = (const float*)d_in[4];
    const float* T     = (const float*)d_in[5];
    float* out = (float*)d_out;

    cudaFuncSetAttribute(k_gemm_mma, cudaFuncAttributeMaxDynamicSharedMemorySize, GEMM_SMEM);

    k_coef<<<Bb, 256>>>(K1, K2, R, T);
    k_row2<<<dim3(IBLK, Bb), 256>>>();
    k_cinv<<<(Bb * Nn + 255) / 256, 256>>>();
    k_conv_f<<<dim3(Cc / 4, Bb), 256>>>(f_src);
    k_gemm_mma<<<dim3(Cc / 128, Nn / 256, Bb), 512, GEMM_SMEM>>>(out);
}